// round 10
// baseline (speedup 1.0000x reference)
#include <cuda_runtime.h>
#include <cstdint>
#include <math.h>

#define Bc 4
#define Lc 2048
#define Dc 256
#define Pc 32
#define Mc 8192
#define NCc 32
#define CHc 64
#define NC2 64
#define CH2 32
#define PIF 3.14159265358979323846f
#define INV_SQRT_P 0.17677669529663688f

// ---------------- scratch (single static device buffer, no allocs) --------
static constexpr size_t OFF_CSUM   = 0;            // 4*64*256 = 65536
static constexpr size_t OFF_OFFP   = 262144;       // 8192*32
static constexpr size_t OFF_PCON   = 524288;       // 2048*32
static constexpr size_t OFF_PC     = 589824;       // 2048*32
static constexpr size_t OFF_PS     = 655360;       // 2048*32
static constexpr size_t OFF_AC     = 720896;       // 8192*64
static constexpr size_t OFF_POSRET = 1245184;      // 8192*32
static constexpr size_t OFF_KQ     = 1769472;      // 8192*64
static constexpr size_t OFF_U      = 2555904;      // 8192*64
static constexpr size_t OFF_GATE   = 5177344;      // 8192
static constexpr size_t OFF_GCUM   = 5185536;      // 8192
static constexpr size_t OFF_GV     = 5193728;      // 8192*256
static constexpr size_t OFF_CTX    = 7290880;      // 8192*256
static constexpr size_t OFF_H      = 11485184;     // 8192*256
static constexpr size_t OFF_DS     = 13615104;     // 4*32*64*256
static constexpr size_t OFF_COMB   = 15712256;     // 8192*256
static constexpr size_t OFF_LN     = 17809408;     // 8192*256
static constexpr size_t OFF_CSUM2  = 19906560;     // 4*32*64
static constexpr size_t TOTAL_F    = 19914752;

__device__ float g_buf[TOTAL_F];

// ---------------- helpers ---------------------------------------------------
__device__ __forceinline__ uint32_t f2tf(float f) {
    uint32_t u;
    asm("cvt.rna.tf32.f32 %0, %1;" : "=r"(u) : "f"(f));
    return u;
}
__device__ __forceinline__ float f2tf_f(float f) { return __uint_as_float(f2tf(f)); }

__device__ __forceinline__ void mma8(float* c, const uint32_t* a, const uint32_t* b) {
    asm volatile(
        "mma.sync.aligned.m16n8k8.row.col.f32.tf32.tf32.f32 "
        "{%0,%1,%2,%3},{%4,%5,%6,%7},{%8,%9},{%0,%1,%2,%3};"
        : "+f"(c[0]), "+f"(c[1]), "+f"(c[2]), "+f"(c[3])
        : "r"(a[0]), "r"(a[1]), "r"(a[2]), "r"(a[3]), "r"(b[0]), "r"(b[1]));
}

__device__ __forceinline__ void cpa16(uint32_t s, const void* g) {
    asm volatile("cp.async.ca.shared.global [%0], [%1], 16;" :: "r"(s), "l"(g));
}

// ---------------- tensor-core GEMM: cp.async 2-stage pipeline ---------------
// ACT: 0 none, 2 gelu, 3 tanh*pi->cos/sin packed, 4 gate fuse.
// SPLIT: 3-mma tf32 correction. CONCAT: A|A2 virtual concat.
// Non-SPLIT path converts fragments with cvt.rna for accuracy.
template<int BM, int BN, int MT, int NT, int ACT, int SPLIT, int CONCAT>
__global__ __launch_bounds__(256) void tgemm_k(
    const float* __restrict__ A, const float* __restrict__ A2,
    const float* __restrict__ W,
    const float* __restrict__ bias, const float* __restrict__ addRow,
    const float* __restrict__ resid, float* __restrict__ C,
    int N, int K)
{
    static_assert(BM == 4 * MT * 16 && BN == 2 * NT * 8, "tile mismatch");
    const int BK = 32, AP = BK + 4, WP = BN + 8;
    extern __shared__ float sm[];
    float* Ab = sm;
    float* Wb = sm + 2 * BM * AP;
    int tid = threadIdx.x;
    int warp = tid >> 5, lane = tid & 31;
    int wm = warp >> 1, wn = warp & 1;
    int g = lane >> 2, tig = lane & 3;
    int bm = blockIdx.y * BM, bn = blockIdx.x * BN;

    float acc[MT][NT][4] = {};

    auto issue = [&](int k0, int s) {
        constexpr int AF4 = BM * BK / 4 / 256;
#pragma unroll
        for (int i = 0; i < AF4; i++) {
            int id = tid + 256 * i;
            int r = id >> 3, c4 = (id & 7) << 2;
            const float* src;
            if (CONCAT)
                src = (k0 < Dc) ? A + (size_t)(bm + r) * Dc + k0 + c4
                                : A2 + (size_t)(bm + r) * Dc + (k0 - Dc) + c4;
            else
                src = A + (size_t)(bm + r) * K + k0 + c4;
            cpa16((uint32_t)__cvta_generic_to_shared(Ab + (s * BM + r) * AP + c4), src);
        }
        constexpr int WF4 = BK * BN / 4 / 256;
#pragma unroll
        for (int i = 0; i < WF4; i++) {
            int id = tid + 256 * i;
            int r = id / (BN / 4), c4 = (id % (BN / 4)) << 2;
            cpa16((uint32_t)__cvta_generic_to_shared(Wb + (s * BK + r) * WP + c4),
                  W + (size_t)(k0 + r) * N + bn + c4);
        }
        asm volatile("cp.async.commit_group;");
    };

    issue(0, 0);
    int nit = K / BK;
    for (int it = 0; it < nit; it++) {
        asm volatile("cp.async.wait_group 0;");
        __syncthreads();
        if (it + 1 < nit) issue((it + 1) * BK, (it + 1) & 1);
        int sb = it & 1;
        const float* Ac = Ab + sb * BM * AP;
        const float* Wc = Wb + sb * BK * WP;
#pragma unroll
        for (int ks = 0; ks < 4; ks++) {
            int kk = ks * 8;
            uint32_t ah[MT][4], al[MT][4];
#pragma unroll
            for (int mt = 0; mt < MT; mt++) {
                int r0 = wm * MT * 16 + mt * 16 + g;
                float f0 = Ac[r0 * AP + kk + tig],       f1 = Ac[(r0 + 8) * AP + kk + tig];
                float f2 = Ac[r0 * AP + kk + tig + 4],   f3 = Ac[(r0 + 8) * AP + kk + tig + 4];
                ah[mt][0] = f2tf(f0); ah[mt][1] = f2tf(f1);
                ah[mt][2] = f2tf(f2); ah[mt][3] = f2tf(f3);
                if (SPLIT) {
                    al[mt][0] = f2tf(f0 - __uint_as_float(ah[mt][0]));
                    al[mt][1] = f2tf(f1 - __uint_as_float(ah[mt][1]));
                    al[mt][2] = f2tf(f2 - __uint_as_float(ah[mt][2]));
                    al[mt][3] = f2tf(f3 - __uint_as_float(ah[mt][3]));
                }
            }
            uint32_t bh[NT][2], bl[NT][2];
#pragma unroll
            for (int nt = 0; nt < NT; nt++) {
                int cn = wn * NT * 8 + nt * 8 + g;
                float f0 = Wc[(kk + tig) * WP + cn], f1 = Wc[(kk + tig + 4) * WP + cn];
                bh[nt][0] = f2tf(f0); bh[nt][1] = f2tf(f1);
                if (SPLIT) {
                    bl[nt][0] = f2tf(f0 - __uint_as_float(bh[nt][0]));
                    bl[nt][1] = f2tf(f1 - __uint_as_float(bh[nt][1]));
                }
            }
#pragma unroll
            for (int mt = 0; mt < MT; mt++)
#pragma unroll
                for (int nt = 0; nt < NT; nt++) {
                    mma8(acc[mt][nt], ah[mt], bh[nt]);
                    if (SPLIT) {
                        mma8(acc[mt][nt], al[mt], bh[nt]);
                        mma8(acc[mt][nt], ah[mt], bl[nt]);
                    }
                }
        }
        __syncthreads();
    }

#pragma unroll
    for (int mt = 0; mt < MT; mt++)
#pragma unroll
        for (int nt = 0; nt < NT; nt++) {
            int r0 = bm + wm * MT * 16 + mt * 16 + g;
            int col = bn + wn * NT * 8 + nt * 8 + 2 * tig;
#pragma unroll
            for (int h2 = 0; h2 < 2; h2++) {
                int row = r0 + h2 * 8;
                int lrow = row & (Lc - 1);
                float v0 = acc[mt][nt][h2 * 2 + 0];
                float v1 = acc[mt][nt][h2 * 2 + 1];
                if (bias) { v0 += bias[col]; v1 += bias[col + 1]; }
                if (ACT == 4) {
                    float gt = addRow[row];
                    v0 *= gt; v1 *= gt;
                } else if (addRow) {
                    v0 += addRow[(size_t)lrow * N + col];
                    v1 += addRow[(size_t)lrow * N + col + 1];
                }
                if (ACT == 2) {
                    v0 = 0.5f * v0 * (1.0f + erff(v0 * 0.70710678118654752f));
                    v1 = 0.5f * v1 * (1.0f + erff(v1 * 0.70710678118654752f));
                }
                if (ACT == 3) {
                    v0 = tanhf(v0) * PIF; v1 = tanhf(v1) * PIF;
                    C[(size_t)row * 64 + col]          = cosf(v0);
                    C[(size_t)row * 64 + 32 + col]     = sinf(v0);
                    C[(size_t)row * 64 + col + 1]      = cosf(v1);
                    C[(size_t)row * 64 + 32 + col + 1] = sinf(v1);
                } else {
                    if (resid) {
                        v0 += resid[(size_t)row * N + col];
                        v1 += resid[(size_t)row * N + col + 1];
                    }
                    *reinterpret_cast<float2*>(&C[(size_t)row * N + col]) =
                        make_float2(v0, v1);
                }
            }
        }
}

static constexpr int smemg(int BM, int BN) { return 2 * (BM * 36 + 32 * (BN + 8)) * 4; }

// ---------------- merged skinny GEMM: x @ [w_mem1v | w_off[:256] | w_key] ---
// N=96 split-tf32, per-segment epilogues: pack-ac / tanh-offset / trig-kq.
static constexpr int M3_SMEM = 2 * (64 * 36 + 32 * 104) * 4;

__global__ __launch_bounds__(256) void merged3_k(
    const float* __restrict__ A,
    const float* __restrict__ w_mem1v, const float* __restrict__ w_off,
    const float* __restrict__ w_key,
    const float* __restrict__ b_mem1v, const float* __restrict__ b_key,
    const float* __restrict__ pcon, const float* __restrict__ pc,
    const float* __restrict__ ps,
    float* __restrict__ ac, float* __restrict__ offp, float* __restrict__ kq)
{
    const int BM = 64, BK = 32, AP = BK + 4, WP = 104, NT = 6;
    extern __shared__ float sm[];
    float* Ab = sm;                   // 2*64*36
    float* Wb = sm + 2 * BM * AP;     // 2*32*104
    int tid = threadIdx.x;
    int warp = tid >> 5, lane = tid & 31;
    int wm = warp >> 1, wn = warp & 1;
    int g = lane >> 2, tig = lane & 3;
    int bm = blockIdx.y * BM;
    const float* segp[3] = { w_mem1v, w_off, w_key };

    float acc[NT][4] = {};

    auto issue = [&](int k0, int s) {
#pragma unroll
        for (int i = 0; i < 2; i++) {
            int id = tid + 256 * i;
            int r = id >> 3, c4 = (id & 7) << 2;
            cpa16((uint32_t)__cvta_generic_to_shared(Ab + (s * BM + r) * AP + c4),
                  A + (size_t)(bm + r) * Dc + k0 + c4);
        }
#pragma unroll
        for (int i = 0; i < 3; i++) {
            int id = tid + 256 * i;
            int r = id / 24, c4 = (id % 24) << 2;   // r in 0..31, c4 in 0..92
            const float* src = segp[c4 >> 5] + (size_t)(k0 + r) * 32 + (c4 & 31);
            cpa16((uint32_t)__cvta_generic_to_shared(Wb + (s * BK + r) * WP + c4), src);
        }
        asm volatile("cp.async.commit_group;");
    };

    issue(0, 0);
    for (int it = 0; it < Dc / BK; it++) {
        asm volatile("cp.async.wait_group 0;");
        __syncthreads();
        if (it + 1 < Dc / BK) issue((it + 1) * BK, (it + 1) & 1);
        int sb = it & 1;
        const float* Ac = Ab + sb * BM * AP;
        const float* Wc = Wb + sb * BK * WP;
#pragma unroll
        for (int ks = 0; ks < 4; ks++) {
            int kk = ks * 8;
            uint32_t ah[4], al[4];
            {
                int r0 = wm * 16 + g;
                float f0 = Ac[r0 * AP + kk + tig],     f1 = Ac[(r0 + 8) * AP + kk + tig];
                float f2 = Ac[r0 * AP + kk + tig + 4], f3 = Ac[(r0 + 8) * AP + kk + tig + 4];
                ah[0] = f2tf(f0); al[0] = f2tf(f0 - __uint_as_float(ah[0]));
                ah[1] = f2tf(f1); al[1] = f2tf(f1 - __uint_as_float(ah[1]));
                ah[2] = f2tf(f2); al[2] = f2tf(f2 - __uint_as_float(ah[2]));
                ah[3] = f2tf(f3); al[3] = f2tf(f3 - __uint_as_float(ah[3]));
            }
            uint32_t bh[NT][2], bl[NT][2];
#pragma unroll
            for (int nt = 0; nt < NT; nt++) {
                int cn = wn * 48 + nt * 8 + g;
                float f0 = Wc[(kk + tig) * WP + cn], f1 = Wc[(kk + tig + 4) * WP + cn];
                bh[nt][0] = f2tf(f0); bl[nt][0] = f2tf(f0 - __uint_as_float(bh[nt][0]));
                bh[nt][1] = f2tf(f1); bl[nt][1] = f2tf(f1 - __uint_as_float(bh[nt][1]));
            }
#pragma unroll
            for (int nt = 0; nt < NT; nt++) {
                mma8(acc[nt], ah, bh[nt]);
                mma8(acc[nt], al, bh[nt]);
                mma8(acc[nt], ah, bl[nt]);
            }
        }
        __syncthreads();
    }

#pragma unroll
    for (int nt = 0; nt < NT; nt++) {
        int col = wn * 48 + nt * 8 + 2 * tig;
        int seg = col >> 5;
#pragma unroll
        for (int h2 = 0; h2 < 2; h2++) {
            int row = bm + wm * 16 + g + h2 * 8;
            int lrow = row & (Lc - 1);
            float v0 = acc[nt][h2 * 2], v1 = acc[nt][h2 * 2 + 1];
            if (seg == 0) {
                int j = col;
                v0 += b_mem1v[j]; v1 += b_mem1v[j + 1];
                ac[(size_t)row * 64 + j]          = pc[lrow * 32 + j] * v0;
                ac[(size_t)row * 64 + 32 + j]     = ps[lrow * 32 + j] * v0;
                ac[(size_t)row * 64 + j + 1]      = pc[lrow * 32 + j + 1] * v1;
                ac[(size_t)row * 64 + 32 + j + 1] = ps[lrow * 32 + j + 1] * v1;
            } else if (seg == 1) {
                int j = col - 32;
                v0 += pcon[lrow * 32 + j]; v1 += pcon[lrow * 32 + j + 1];
                offp[(size_t)row * 32 + j]     = tanhf(v0) * PIF;
                offp[(size_t)row * 32 + j + 1] = tanhf(v1) * PIF;
            } else {
                int j = col - 64;
                v0 += b_key[j]; v1 += b_key[j + 1];
                v0 = tanhf(v0) * PIF; v1 = tanhf(v1) * PIF;
                kq[(size_t)row * 64 + j]          = cosf(v0);
                kq[(size_t)row * 64 + 32 + j]     = sinf(v0);
                kq[(size_t)row * 64 + j + 1]      = cosf(v1);
                kq[(size_t)row * 64 + 32 + j + 1] = sinf(v1);
            }
        }
    }
}

// ---------------- pos precompute -------------------------------------------
__global__ void pos_pre_k(const float* __restrict__ ph, const float* __restrict__ w_off,
                          const float* __restrict__ b_off,
                          float* __restrict__ pc, float* __restrict__ ps,
                          float* __restrict__ pcon)
{
    int idx = blockIdx.x * blockDim.x + threadIdx.x;
    if (idx >= Lc * Pc) return;
    int l = idx >> 5, p = idx & 31;
    float s = b_off[p];
#pragma unroll
    for (int q = 0; q < Pc; q++) s += ph[l * Pc + q] * w_off[(Dc + q) * Pc + p];
    pcon[idx] = s;
    float v = ph[idx];
    pc[idx] = cosf(v);
    ps[idx] = sinf(v);
}

// ---------------- fused gate: dot + sigmoid + in-block cumsum ---------------
__global__ __launch_bounds__(1024) void gate_all_k(
    const float* __restrict__ x, const float* __restrict__ w,
    const float* __restrict__ bsc, float* __restrict__ gate,
    float* __restrict__ gcum)
{
    __shared__ float gs[2048];
    __shared__ float wsum[32];
    int b = blockIdx.x;
    int tid = threadIdx.x, warp = tid >> 5, lane = tid & 31;
    const float* xb = x + (size_t)b * Lc * Dc;
    float bias = bsc[0];
    float wreg[8];
#pragma unroll
    for (int i = 0; i < 8; i++) wreg[i] = w[lane + i * 32];
    for (int r0 = warp * 64; r0 < warp * 64 + 64; r0 += 8) {
        float acc[8] = {};
#pragma unroll
        for (int j = 0; j < 8; j++) {
            const float* xr = xb + (size_t)(r0 + j) * Dc + lane;
#pragma unroll
            for (int i = 0; i < 8; i++) acc[j] += xr[i * 32] * wreg[i];
        }
#pragma unroll
        for (int j = 0; j < 8; j++) {
            float s = acc[j];
#pragma unroll
            for (int o = 16; o; o >>= 1) s += __shfl_xor_sync(0xffffffffu, s, o);
            if (lane == 0) gs[r0 + j] = 1.0f / (1.0f + expf(-(s + bias)));
        }
    }
    __syncthreads();
    float a0 = gs[tid * 2], a1 = gs[tid * 2 + 1];
    float tsum = a0 + a1;
    float sc = tsum;
#pragma unroll
    for (int o = 1; o < 32; o <<= 1) {
        float v = __shfl_up_sync(0xffffffffu, sc, o);
        if (lane >= o) sc += v;
    }
    if (lane == 31) wsum[warp] = sc;
    __syncthreads();
    if (warp == 0) {
        float w0 = wsum[lane];
#pragma unroll
        for (int o = 1; o < 32; o <<= 1) {
            float v = __shfl_up_sync(0xffffffffu, w0, o);
            if (lane >= o) w0 += v;
        }
        wsum[lane] = w0;
    }
    __syncthreads();
    float off = (warp ? wsum[warp - 1] : 0.0f) + (sc - tsum);
    gate[b * Lc + tid * 2]     = a0;
    gate[b * Lc + tid * 2 + 1] = a1;
    gcum[b * Lc + tid * 2]     = off + a0;
    gcum[b * Lc + tid * 2 + 1] = off + a0 + a1;
}

// ---------------- x scan (2 kernels; prefix inlined into apply) -------------
__global__ void xscan_sums_k(const float* __restrict__ in, float* __restrict__ csum)
{
    int bc = blockIdx.x, b = bc / NC2, c = bc % NC2, f = threadIdx.x;
    const float* p = in + ((size_t)b * Lc + c * CH2) * 256 + f;
    float s = 0.f;
#pragma unroll
    for (int i = 0; i < CH2; i++) s += p[(size_t)i * 256];
    csum[(size_t)bc * 256 + f] = s;
}

__global__ void xscan_apply_k(const float* __restrict__ in, const float* __restrict__ csum,
                              float* __restrict__ ctx)
{
    int bc = blockIdx.x, b = bc / NC2, c = bc % NC2, f = threadIdx.x;
    float carry = 0.f;
    for (int j = 0; j < c; j++) carry += csum[((size_t)b * NC2 + j) * 256 + f];
    const float* p = in + ((size_t)b * Lc + c * CH2) * 256 + f;
    float* q = ctx + ((size_t)b * Lc + c * CH2) * 256 + f;
#pragma unroll 8
    for (int i = 0; i < CH2; i++) {
        carry += p[(size_t)i * 256];
        q[(size_t)i * 256] = carry * (1.0f / (float)(c * CH2 + i + 1));
    }
}

// ---------------- ac scan (2 kernels; prefix inlined) -----------------------
__global__ void ac_sums_k(const float* __restrict__ in, float* __restrict__ csum)
{
    int bc = blockIdx.x, b = bc / NCc, c = bc % NCc, f = threadIdx.x;
    const float* p = in + ((size_t)b * Lc + c * CHc) * 64 + f;
    float s = 0.f;
#pragma unroll 8
    for (int i = 0; i < CHc; i++) s += p[(size_t)i * 64];
    csum[(size_t)bc * 64 + f] = s;
}

// fused: inline prefix + chunk cumsum (to shared) + posret epilogue
__global__ __launch_bounds__(64) void ac_apply_posret_k(
    const float* __restrict__ ac, const float* __restrict__ csum,
    const float* __restrict__ offp, const float* __restrict__ pc,
    const float* __restrict__ ps, float* __restrict__ pr)
{
    __shared__ float sh[64][65];
    int bc = blockIdx.x, b = bc / NCc, c = bc % NCc, f = threadIdx.x;
    size_t rowbase = (size_t)bc * 64;
    float carry = 0.f;
    for (int j = 0; j < c; j++) carry += csum[((size_t)b * NCc + j) * 64 + f];
    const float* p = ac + rowbase * 64 + f;
#pragma unroll 8
    for (int i = 0; i < CHc; i++) {
        carry += p[(size_t)i * 64];
        sh[i][f] = carry;
    }
    __syncthreads();
#pragma unroll
    for (int j = 0; j < 32; j++) {
        int idx = j * 64 + f;
        int i = idx >> 5, pp = idx & 31;
        size_t m = rowbase + i;
        int l = (int)(m & (Lc - 1));
        float o = offp[m * 32 + pp];
        float oc = cosf(o), os = sinf(o);
        float pcv = pc[l * 32 + pp], psv = ps[l * 32 + pp];
        float qc = pcv * oc - psv * os;
        float qs = psv * oc + pcv * os;
        pr[m * 32 + pp] = (sh[i][pp] * qc + sh[i][32 + pp] * qs) * INV_SQRT_P;
    }
}

// ---------------- chunk state delta via tf32 mma ---------------------------
__global__ __launch_bounds__(256) void chunk_delta_k(const float* __restrict__ U,
                                                     const float* __restrict__ GV,
                                                     float* __restrict__ dS)
{
    __shared__ float Us[64][72];
    __shared__ float Gs[64][72];
    int bc = blockIdx.x;
    size_t rowbase = (size_t)bc * 64;
    int tid = threadIdx.x;
    int warp = tid >> 5, lane = tid & 31;
    int wm = warp >> 2, wn = warp & 3;
    int g = lane >> 2, tig = lane & 3;

#pragma unroll
    for (int i = 0; i < 4; i++) {
        int id = tid + 256 * i;
        int t = id >> 4, f = (id & 15) << 2;
        float4 v = *reinterpret_cast<const float4*>(U + (rowbase + t) * 64 + f);
        v.x = f2tf_f(v.x); v.y = f2tf_f(v.y); v.z = f2tf_f(v.z); v.w = f2tf_f(v.w);
        *reinterpret_cast<float4*>(&Us[t][f]) = v;
    }

    for (int dt = 0; dt < 4; dt++) {
        __syncthreads();
#pragma unroll
        for (int i = 0; i < 4; i++) {
            int id = tid + 256 * i;
            int t = id >> 4, d = (id & 15) << 2;
            float4 v = *reinterpret_cast<const float4*>(GV + (rowbase + t) * 256 + dt * 64 + d);
            v.x = f2tf_f(v.x); v.y = f2tf_f(v.y); v.z = f2tf_f(v.z); v.w = f2tf_f(v.w);
            *reinterpret_cast<float4*>(&Gs[t][d]) = v;
        }
        __syncthreads();

        float acc[2][2][4] = {};
#pragma unroll
        for (int ks = 0; ks < 8; ks++) {
            int kk = ks * 8;
            uint32_t a[2][4], b[2][2];
#pragma unroll
            for (int mt = 0; mt < 2; mt++) {
                int f0 = wm * 32 + mt * 16 + g;
                a[mt][0] = __float_as_uint(Us[kk + tig][f0]);
                a[mt][1] = __float_as_uint(Us[kk + tig][f0 + 8]);
                a[mt][2] = __float_as_uint(Us[kk + tig + 4][f0]);
                a[mt][3] = __float_as_uint(Us[kk + tig + 4][f0 + 8]);
            }
#pragma unroll
            for (int nt = 0; nt < 2; nt++) {
                int d0 = wn * 16 + nt * 8 + g;
                b[nt][0] = __float_as_uint(Gs[kk + tig][d0]);
                b[nt][1] = __float_as_uint(Gs[kk + tig + 4][d0]);
            }
#pragma unroll
            for (int mt = 0; mt < 2; mt++)
#pragma unroll
                for (int nt = 0; nt < 2; nt++) mma8(acc[mt][nt], a[mt], b[nt]);
        }
#pragma unroll
        for (int mt = 0; mt < 2; mt++)
#pragma unroll
            for (int nt = 0; nt < 2; nt++) {
                int f0 = wm * 32 + mt * 16 + g;
                int d = dt * 64 + wn * 16 + nt * 8 + 2 * tig;
#pragma unroll
                for (int h2 = 0; h2 < 2; h2++) {
                    *reinterpret_cast<float2*>(&dS[((size_t)bc * 64 + f0 + h2 * 8) * 256 + d]) =
                        make_float2(acc[mt][nt][h2 * 2], acc[mt][nt][h2 * 2 + 1]);
                }
            }
    }
}

// ---------------- exclusive prefix of chunk states (pipelined) --------------
__global__ void state_prefix_k(float* __restrict__ dS)
{
    int idx = blockIdx.x * blockDim.x + threadIdx.x;
    int b = idx >> 14;
    int fd = idx & 16383;
    size_t base = (size_t)b * NCc * 16384 + fd;
    float carry = 0.f;
    float v = dS[base];
    for (int c = 0; c < NCc; c++) {
        size_t o = base + (size_t)c * 16384;
        float vn = (c + 1 < NCc) ? dS[o + 16384] : 0.f;
        dS[o] = carry;
        carry += v;
        v = vn;
    }
}

// ---------------- kv pass3 via tf32 mma + fused layernorm -------------------
static constexpr int P3_PITCH = 68;
static constexpr size_t SMEM_P3 = 5 * 64 * P3_PITCH * sizeof(float);

__global__ __launch_bounds__(256) void kv_pass3_mma_k(
    const float* __restrict__ Kq, const float* __restrict__ U,
    const float* __restrict__ GV, const float* __restrict__ Spre,
    const float* __restrict__ gcum, const float* __restrict__ comb,
    const float* __restrict__ lng, const float* __restrict__ lnbv,
    float* __restrict__ outb)
{
    extern __shared__ float dyn[];
    float (*Kqs)[P3_PITCH] = reinterpret_cast<float(*)[P3_PITCH]>(dyn);
    float (*Us)[P3_PITCH]  = reinterpret_cast<float(*)[P3_PITCH]>(dyn + 64 * P3_PITCH);
    float (*Ss)[P3_PITCH]  = reinterpret_cast<float(*)[P3_PITCH]>(dyn + 2 * 64 * P3_PITCH);
    float (*P1)[P3_PITCH]  = reinterpret_cast<float(*)[P3_PITCH]>(dyn + 3 * 64 * P3_PITCH);
    float (*P2)[P3_PITCH]  = reinterpret_cast<float(*)[P3_PITCH]>(dyn + 4 * 64 * P3_PITCH);
    __shared__ float ws[4][64], ws2[4][64];

    int bc = blockIdx.x;
    size_t rowbase = (size_t)bc * 64;
    int tid = threadIdx.x;
    int warp = tid >> 5, lane = tid & 31;
    int wm = warp >> 2, wn = warp & 3;
    int g = lane >> 2, tig = lane & 3;

#pragma unroll
    for (int i = 0; i < 4; i++) {
        int id = tid + 256 * i;
        int t = id >> 4, f = (id & 15) << 2;
        float4 v = *reinterpret_cast<const float4*>(Kq + (rowbase + t) * 64 + f);
        v.x = f2tf_f(v.x); v.y = f2tf_f(v.y); v.z = f2tf_f(v.z); v.w = f2tf_f(v.w);
        *reinterpret_cast<float4*>(&Kqs[t][f]) = v;
        float4 w = *reinterpret_cast<const float4*>(U + (rowbase + t) * 64 + f);
        w.x = f2tf_f(w.x); w.y = f2tf_f(w.y); w.z = f2tf_f(w.z); w.w = f2tf_f(w.w);
        *reinterpret_cast<float4*>(&Us[t][f]) = w;
    }
    __syncthreads();

    {
        float sacc[2][2][4] = {};
#pragma unroll
        for (int ks = 0; ks < 8; ks++) {
            int kk = ks * 8;
            uint32_t a[2][4], b[2][2];
#pragma unroll
            for (int mt = 0; mt < 2; mt++) {
                int r0 = wm * 32 + mt * 16 + g;
                a[mt][0] = __float_as_uint(Kqs[r0][kk + tig]);
                a[mt][1] = __float_as_uint(Kqs[r0 + 8][kk + tig]);
                a[mt][2] = __float_as_uint(Kqs[r0][kk + tig + 4]);
                a[mt][3] = __float_as_uint(Kqs[r0 + 8][kk + tig + 4]);
            }
#pragma unroll
            for (int nt = 0; nt < 2; nt++) {
                int cn = wn * 16 + nt * 8 + g;
                b[nt][0] = __float_as_uint(Us[cn][kk + tig]);
                b[nt][1] = __float_as_uint(Us[cn][kk + tig + 4]);
            }
#pragma unroll
            for (int mt = 0; mt < 2; mt++)
#pragma unroll
                for (int nt = 0; nt < 2; nt++) mma8(sacc[mt][nt], a[mt], b[nt]);
        }
#pragma unroll
        for (int mt = 0; mt < 2; mt++)
#pragma unroll
            for (int nt = 0; nt < 2; nt++)
#pragma unroll
                for (int h2 = 0; h2 < 2; h2++) {
                    int row = wm * 32 + mt * 16 + h2 * 8 + g;
                    int col = wn * 16 + nt * 8 + 2 * tig;
                    float v0 = (col     <= row) ? sacc[mt][nt][h2 * 2]     : 0.f;
                    float v1 = (col + 1 <= row) ? sacc[mt][nt][h2 * 2 + 1] : 0.f;
                    Ss[row][col]     = f2tf_f(v0);
                    Ss[row][col + 1] = f2tf_f(v1);
                }
    }
    __syncthreads();

    float val[4][2][2][4];
#pragma unroll
    for (int p = 0; p < 4; p++)
#pragma unroll
        for (int mt = 0; mt < 2; mt++)
#pragma unroll
            for (int nt = 0; nt < 2; nt++)
#pragma unroll
                for (int j = 0; j < 4; j++) val[p][mt][nt][j] = 0.f;

    for (int p = 0; p < 4; p++) {
#pragma unroll
        for (int i = 0; i < 4; i++) {
            int id = tid + 256 * i;
            int t = id >> 4, d = (id & 15) << 2;
            float4 v = *reinterpret_cast<const float4*>(GV + (rowbase + t) * 256 + p * 64 + d);
            v.x = f2tf_f(v.x); v.y = f2tf_f(v.y); v.z = f2tf_f(v.z); v.w = f2tf_f(v.w);
            *reinterpret_cast<float4*>(&P1[t][d]) = v;
            float4 w = *reinterpret_cast<const float4*>(Spre + ((size_t)bc * 64 + t) * 256 + p * 64 + d);
            w.x = f2tf_f(w.x); w.y = f2tf_f(w.y); w.z = f2tf_f(w.z); w.w = f2tf_f(w.w);
            *reinterpret_cast<float4*>(&P2[t][d]) = w;
        }
        __syncthreads();
#pragma unroll
        for (int ks = 0; ks < 8; ks++) {
            int kk = ks * 8;
            uint32_t a1[2][4], a2[2][4], b1[2][2], b2[2][2];
#pragma unroll
            for (int mt = 0; mt < 2; mt++) {
                int r0 = wm * 32 + mt * 16 + g;
                a1[mt][0] = __float_as_uint(Ss[r0][kk + tig]);
                a1[mt][1] = __float_as_uint(Ss[r0 + 8][kk + tig]);
                a1[mt][2] = __float_as_uint(Ss[r0][kk + tig + 4]);
                a1[mt][3] = __float_as_uint(Ss[r0 + 8][kk + tig + 4]);
                a2[mt][0] = __float_as_uint(Kqs[r0][kk + tig]);
                a2[mt][1] = __float_as_uint(Kqs[r0 + 8][kk + tig]);
                a2[mt][2] = __float_as_uint(Kqs[r0][kk + tig + 4]);
                a2[mt][3] = __float_as_uint(Kqs[r0 + 8][kk + tig + 4]);
            }
#pragma unroll
            for (int nt = 0; nt < 2; nt++) {
                int cn = wn * 16 + nt * 8 + g;
                b1[nt][0] = __float_as_uint(P1[kk + tig][cn]);
                b1[nt][1] = __float_as_uint(P1[kk + tig + 4][cn]);
                b2[nt][0] = __float_as_uint(P2[kk + tig][cn]);
                b2[nt][1] = __float_as_uint(P2[kk + tig + 4][cn]);
            }
#pragma unroll
            for (int mt = 0; mt < 2; mt++)
#pragma unroll
                for (int nt = 0; nt < 2; nt++) {
                    mma8(val[p][mt][nt], a1[mt], b1[nt]);
                    mma8(val[p][mt][nt], a2[mt], b2[nt]);
                }
        }
        __syncthreads();
    }

    float scl4[4];
#pragma unroll
    for (int mt = 0; mt < 2; mt++)
#pragma unroll
        for (int h2 = 0; h2 < 2; h2++) {
            int row = wm * 32 + mt * 16 + h2 * 8 + g;
            float gc = gcum[rowbase + row];
            scl4[mt * 2 + h2] = rsqrtf(fmaxf(gc, 1.0f)) * INV_SQRT_P;
        }
    float s[4] = {}, s2[4] = {};
#pragma unroll
    for (int p = 0; p < 4; p++)
#pragma unroll
        for (int mt = 0; mt < 2; mt++)
#pragma unroll
            for (int nt = 0; nt < 2; nt++)
#pragma unroll
                for (int h2 = 0; h2 < 2; h2++) {
                    int row = wm * 32 + mt * 16 + h2 * 8 + g;
                    int col = p * 64 + wn * 16 + nt * 8 + 2 * tig;
                    int slot = mt * 2 + h2;
                    float2 cb = *reinterpret_cast<const float2*>(
                        &comb[(rowbase + row) * 256 + col]);
                    float v0 = cb.x + val[p][mt][nt][h2 * 2]     * scl4[slot];
                    float v1 = cb.y + val[p][mt][nt][h2 * 2 + 1] * scl4[slot];
                    val[p][mt][nt][h2 * 2] = v0;
                    val[p][mt][nt][h2 * 2 + 1] = v1;
                    s[slot] += v0 + v1;
                    s2[slot] += v0 * v0 + v1 * v1;
                }
#pragma unroll
    for (int o = 1; o <= 2; o <<= 1)
#pragma unroll
        for (int i = 0; i < 4; i++) {
            s[i]  += __shfl_xor_sync(0xffffffffu, s[i],  o);
            s2[i] += __shfl_xor_sync(0xffffffffu, s2[i], o);
        }
    if (tig == 0) {
#pragma unroll
        for (int mt = 0; mt < 2; mt++)
#pragma unroll
            for (int h2 = 0; h2 < 2; h2++) {
                int row = wm * 32 + mt * 16 + h2 * 8 + g;
                ws[wn][row]  = s[mt * 2 + h2];
                ws2[wn][row] = s2[mt * 2 + h2];
            }
    }
    __syncthreads();
    float mean4[4], rstd4[4];
#pragma unroll
    for (int mt = 0; mt < 2; mt++)
#pragma unroll
        for (int h2 = 0; h2 < 2; h2++) {
            int row = wm * 32 + mt * 16 + h2 * 8 + g;
            float St = ws[0][row] + ws[1][row] + ws[2][row] + ws[3][row];
            float S2t = ws2[0][row] + ws2[1][row] + ws2[2][row] + ws2[3][row];
            float mean = St * (1.0f / 256.0f);
            float var = S2t * (1.0f / 256.0f) - mean * mean;
            mean4[mt * 2 + h2] = mean;
            rstd4[mt * 2 + h2] = rsqrtf(var + 1e-5f);
        }
#pragma unroll
    for (int p = 0; p < 4; p++)
#pragma unroll
        for (int nt = 0; nt < 2; nt++) {
            int col = p * 64 + wn * 16 + nt * 8 + 2 * tig;
            float g0 = lng[col], g1 = lng[col + 1];
            float b0 = lnbv[col], b1 = lnbv[col + 1];
#pragma unroll
            for (int mt = 0; mt < 2; mt++)
#pragma unroll
                for (int h2 = 0; h2 < 2; h2++) {
                    int row = wm * 32 + mt * 16 + h2 * 8 + g;
                    int slot = mt * 2 + h2;
                    float v0 = (val[p][mt][nt][h2 * 2]     - mean4[slot]) * rstd4[slot] * g0 + b0;
                    float v1 = (val[p][mt][nt][h2 * 2 + 1] - mean4[slot]) * rstd4[slot] * g1 + b1;
                    *reinterpret_cast<float2*>(&outb[(rowbase + row) * 256 + col]) =
                        make_float2(v0, v1);
                }
        }
}

// ---------------- stream/event context (created once, outside capture) -----
namespace {
struct Ctx {
    cudaStream_t s1, s2;
    cudaEvent_t eR1, eR2, eGV, eA;
    Ctx() {
        cudaStreamCreateWithFlags(&s1, cudaStreamNonBlocking);
        cudaStreamCreateWithFlags(&s2, cudaStreamNonBlocking);
        cudaEventCreateWithFlags(&eR1, cudaEventDisableTiming);
        cudaEventCreateWithFlags(&eR2, cudaEventDisableTiming);
        cudaEventCreateWithFlags(&eGV, cudaEventDisableTiming);
        cudaEventCreateWithFlags(&eA, cudaEventDisableTiming);
        cudaFuncSetAttribute(kv_pass3_mma_k,
                             cudaFuncAttributeMaxDynamicSharedMemorySize, (int)SMEM_P3);
        cudaFuncSetAttribute(merged3_k,
                             cudaFuncAttributeMaxDynamicSharedMemorySize, M3_SMEM);
        cudaFuncSetAttribute(tgemm_k<128, 64, 2, 4, 0, 0, 0>,
                             cudaFuncAttributeMaxDynamicSharedMemorySize, smemg(128, 64));
        cudaFuncSetAttribute(tgemm_k<128, 64, 2, 4, 4, 0, 0>,
                             cudaFuncAttributeMaxDynamicSharedMemorySize, smemg(128, 64));
        cudaFuncSetAttribute(tgemm_k<128, 64, 2, 4, 2, 0, 1>,
                             cudaFuncAttributeMaxDynamicSharedMemorySize, smemg(128, 64));
        cudaFuncSetAttribute(tgemm_k<64, 32, 1, 2, 3, 1, 0>,
                             cudaFuncAttributeMaxDynamicSharedMemorySize, smemg(64, 32));
    }
};
Ctx& C() { static Ctx c; return c; }
}

// ---------------- host launch -----------------------------------------------
extern "C" void kernel_launch(void* const* d_in, const int* in_sizes, int n_in,
                              void* d_out, int out_size)
{
    (void)in_sizes; (void)n_in; (void)out_size;
    const float* x        = (const float*)d_in[0];
    const float* pos_ph   = (const float*)d_in[1];
    const float* w_mem1v  = (const float*)d_in[2];
    const float* b_mem1v  = (const float*)d_in[3];
    const float* w_mem1o  = (const float*)d_in[4];
    const float* b_mem1o  = (const float*)d_in[5];
    const float* w_off    = (const float*)d_in[6];
    const float* b_off    = (const float*)d_in[7];
    const float* w_key    = (const float*)d_in[8];
    const float* b_key    = (const float*)d_in[9];
    const float* w_val    = (const float*)d_in[10];
    const float* b_val    = (const float*)d_in[11];
    const float* w_sk1    = (const float*)d_in[12];
    const float* b_sk1    = (const float*)d_in[13];
    const float* w_sk2    = (const float*)d_in[14];
    const float* b_sk2    = (const float*)d_in[15];
    const float* w_gate   = (const float*)d_in[16];
    const float* b_gate   = (const float*)d_in[17];
    const float* ln_g     = (const float*)d_in[18];
    const float* ln_b     = (const float*)d_in[19];
    const float* w_out    = (const float*)d_in[20];
    const float* b_out    = (const float*)d_in[21];
    float* out = (float*)d_out;

    float* buf = nullptr;
    cudaGetSymbolAddress((void**)&buf, g_buf);
    float* csum  = buf + OFF_CSUM;
    float* offp  = buf + OFF_OFFP;
    float* pcon  = buf + OFF_PCON;
    float* pc    = buf + OFF_PC;
    float* ps    = buf + OFF_PS;
    float* ac    = buf + OFF_AC;
    float* pr    = buf + OFF_POSRET;
    float* kq    = buf + OFF_KQ;
    float* u     = buf + OFF_U;
    float* gate  = buf + OFF_GATE;
    float* gcum  = buf + OFF_GCUM;
    float* gv    = buf + OFF_GV;
    float* ctx   = buf + OFF_CTX;
    float* h     = buf + OFF_H;
    float* csum2 = buf + OFF_CSUM2;
    float* dS    = buf + OFF_DS;
    float* comb  = buf + OFF_COMB;
    float* lnb   = buf + OFF_LN;

    Ctx& c = C();
    dim3 gS(1, Mc / 64);
    dim3 gW(4, Mc / 128);
    const int SS = smemg(64, 32), SW = smemg(128, 64);

    // fork
    cudaEventRecord(c.eR1, 0);
    cudaStreamWaitEvent(c.s1, c.eR1, 0);
    cudaEventRecord(c.eR2, 0);
    cudaStreamWaitEvent(c.s2, c.eR2, 0);

    // ---- path A (s1): merged x-projections + mem1 ----
    pos_pre_k<<<(Lc * Pc) / 256, 256, 0, c.s1>>>(pos_ph, w_off, b_off, pc, ps, pcon);
    merged3_k<<<gS, 256, M3_SMEM, c.s1>>>(x, w_mem1v, w_off, w_key, b_mem1v, b_key,
                                          pcon, pc, ps, ac, offp, kq);
    ac_sums_k<<<Bc * NCc, 64, 0, c.s1>>>(ac, csum2);
    ac_apply_posret_k<<<Bc * NCc, 64, 0, c.s1>>>(ac, csum2, offp, pc, ps, pr);
    tgemm_k<128, 64, 2, 4, 0, 0, 0><<<gW, 256, SW, c.s1>>>(pr, nullptr, w_mem1o, b_mem1o, nullptr, nullptr, comb, Dc, Pc);
    cudaEventRecord(c.eA, c.s1);

    // ---- path B (s2): gate + gated values ----
    gate_all_k<<<Bc, 1024, 0, c.s2>>>(x, w_gate, b_gate, gate, gcum);
    tgemm_k<128, 64, 2, 4, 4, 0, 0><<<gW, 256, SW, c.s2>>>(x, nullptr, w_val, b_val, gate, nullptr, gv, Dc, Dc);
    cudaEventRecord(c.eGV, c.s2);

    // ---- path D (default): storage phases + attention ----
    xscan_sums_k<<<Bc * NC2, 256>>>(x, csum);
    xscan_apply_k<<<Bc * NC2, 256>>>(x, csum, ctx);
    tgemm_k<128, 64, 2, 4, 2, 0, 1><<<gW, 256, SW>>>(x, ctx, w_sk1, b_sk1, nullptr, nullptr, h, Dc, 2 * Dc);
    tgemm_k<64, 32, 1, 2, 3, 1, 0><<<gS, 256, SS>>>(h, nullptr, w_sk2, b_sk2, nullptr, nullptr, u, Pc, Dc);
    cudaStreamWaitEvent(0, c.eGV, 0);
    chunk_delta_k<<<Bc * NCc, 256>>>(u, gv, dS);
    state_prefix_k<<<(Bc * 64 * 256) / 256, 256>>>(dS);
    cudaStreamWaitEvent(0, c.eA, 0);
    kv_pass3_mma_k<<<Bc * NCc, 256, SMEM_P3>>>(kq, u, gv, dS, gcum, comb, ln_g, ln_b, lnb);
    tgemm_k<128, 64, 2, 4, 0, 0, 0><<<gW, 256, SW>>>(lnb, nullptr, w_out, b_out, nullptr, x, out, Dc, Dc);
}

// round 12
// speedup vs baseline: 1.4085x; 1.4085x over previous
#include <cuda_runtime.h>
#include <cstdint>
#include <math.h>

#define Bc 4
#define Lc 2048
#define Dc 256
#define Pc 32
#define Mc 8192
#define NCc 32
#define CHc 64
#define NC2 64
#define CH2 32
#define PIF 3.14159265358979323846f
#define INV_SQRT_P 0.17677669529663688f

// ---------------- scratch (single static device buffer, no allocs) --------
static constexpr size_t OFF_CSUM   = 0;            // 4*64*256
static constexpr size_t OFF_OFFP   = 262144;       // 8192*32
static constexpr size_t OFF_PCON   = 524288;       // 2048*32
static constexpr size_t OFF_PC     = 589824;       // 2048*32
static constexpr size_t OFF_PS     = 655360;       // 2048*32
static constexpr size_t OFF_AC     = 720896;       // 8192*64
static constexpr size_t OFF_POSRET = 1245184;      // 8192*32
static constexpr size_t OFF_KQ     = 1769472;      // 8192*64
static constexpr size_t OFF_U      = 2555904;      // 8192*64
static constexpr size_t OFF_GATE   = 5177344;      // 8192
static constexpr size_t OFF_GCUM   = 5185536;      // 8192
static constexpr size_t OFF_GV     = 5193728;      // 8192*256
static constexpr size_t OFF_CTX    = 7290880;      // 8192*256
static constexpr size_t OFF_H      = 11485184;     // 8192*256
static constexpr size_t OFF_DS     = 13615104;     // 4*32*64*256
static constexpr size_t OFF_COMB   = 15712256;     // 8192*256
static constexpr size_t OFF_LN     = 17809408;     // 8192*256
static constexpr size_t OFF_CSUM2  = 19906560;     // 4*32*64
static constexpr size_t TOTAL_F    = 19914752;

__device__ float g_buf[TOTAL_F];

// ---------------- helpers ---------------------------------------------------
__device__ __forceinline__ uint32_t f2tf(float f) {
    uint32_t u;
    asm("cvt.rna.tf32.f32 %0, %1;" : "=r"(u) : "f"(f));
    return u;
}
__device__ __forceinline__ float f2tf_f(float f) { return __uint_as_float(f2tf(f)); }

__device__ __forceinline__ void mma8(float* c, const uint32_t* a, const uint32_t* b) {
    asm volatile(
        "mma.sync.aligned.m16n8k8.row.col.f32.tf32.tf32.f32 "
        "{%0,%1,%2,%3},{%4,%5,%6,%7},{%8,%9},{%0,%1,%2,%3};"
        : "+f"(c[0]), "+f"(c[1]), "+f"(c[2]), "+f"(c[3])
        : "r"(a[0]), "r"(a[1]), "r"(a[2]), "r"(a[3]), "r"(b[0]), "r"(b[1]));
}

__device__ __forceinline__ void cpa16(uint32_t s, const void* g) {
    asm volatile("cp.async.ca.shared.global [%0], [%1], 16;" :: "r"(s), "l"(g));
}

// ---------------- tensor-core GEMM: cp.async 2-stage pipeline ---------------
template<int BM, int BN, int MT, int NT, int ACT, int SPLIT, int CONCAT>
__global__ __launch_bounds__(256) void tgemm_k(
    const float* __restrict__ A, const float* __restrict__ A2,
    const float* __restrict__ W,
    const float* __restrict__ bias, const float* __restrict__ addRow,
    const float* __restrict__ resid, float* __restrict__ C,
    int N, int K)
{
    static_assert(BM == 4 * MT * 16 && BN == 2 * NT * 8, "tile mismatch");
    const int BK = 32, AP = BK + 4, WP = BN + 8;
    extern __shared__ float sm[];
    float* Ab = sm;
    float* Wb = sm + 2 * BM * AP;
    int tid = threadIdx.x;
    int warp = tid >> 5, lane = tid & 31;
    int wm = warp >> 1, wn = warp & 1;
    int g = lane >> 2, tig = lane & 3;
    int bm = blockIdx.y * BM, bn = blockIdx.x * BN;

    float acc[MT][NT][4] = {};

    auto issue = [&](int k0, int s) {
        constexpr int AF4 = BM * BK / 4 / 256;
#pragma unroll
        for (int i = 0; i < AF4; i++) {
            int id = tid + 256 * i;
            int r = id >> 3, c4 = (id & 7) << 2;
            const float* src;
            if (CONCAT)
                src = (k0 < Dc) ? A + (size_t)(bm + r) * Dc + k0 + c4
                                : A2 + (size_t)(bm + r) * Dc + (k0 - Dc) + c4;
            else
                src = A + (size_t)(bm + r) * K + k0 + c4;
            cpa16((uint32_t)__cvta_generic_to_shared(Ab + (s * BM + r) * AP + c4), src);
        }
        constexpr int WF4 = BK * BN / 4 / 256;
#pragma unroll
        for (int i = 0; i < WF4; i++) {
            int id = tid + 256 * i;
            int r = id / (BN / 4), c4 = (id % (BN / 4)) << 2;
            cpa16((uint32_t)__cvta_generic_to_shared(Wb + (s * BK + r) * WP + c4),
                  W + (size_t)(k0 + r) * N + bn + c4);
        }
        asm volatile("cp.async.commit_group;");
    };

    issue(0, 0);
    int nit = K / BK;
    for (int it = 0; it < nit; it++) {
        asm volatile("cp.async.wait_group 0;");
        __syncthreads();
        if (it + 1 < nit) issue((it + 1) * BK, (it + 1) & 1);
        int sb = it & 1;
        const float* Ac = Ab + sb * BM * AP;
        const float* Wc = Wb + sb * BK * WP;
#pragma unroll
        for (int ks = 0; ks < 4; ks++) {
            int kk = ks * 8;
            uint32_t ah[MT][4], al[MT][4];
#pragma unroll
            for (int mt = 0; mt < MT; mt++) {
                int r0 = wm * MT * 16 + mt * 16 + g;
                float f0 = Ac[r0 * AP + kk + tig],       f1 = Ac[(r0 + 8) * AP + kk + tig];
                float f2 = Ac[r0 * AP + kk + tig + 4],   f3 = Ac[(r0 + 8) * AP + kk + tig + 4];
                ah[mt][0] = f2tf(f0); ah[mt][1] = f2tf(f1);
                ah[mt][2] = f2tf(f2); ah[mt][3] = f2tf(f3);
                if (SPLIT) {
                    al[mt][0] = f2tf(f0 - __uint_as_float(ah[mt][0]));
                    al[mt][1] = f2tf(f1 - __uint_as_float(ah[mt][1]));
                    al[mt][2] = f2tf(f2 - __uint_as_float(ah[mt][2]));
                    al[mt][3] = f2tf(f3 - __uint_as_float(ah[mt][3]));
                }
            }
            uint32_t bh[NT][2], bl[NT][2];
#pragma unroll
            for (int nt = 0; nt < NT; nt++) {
                int cn = wn * NT * 8 + nt * 8 + g;
                float f0 = Wc[(kk + tig) * WP + cn], f1 = Wc[(kk + tig + 4) * WP + cn];
                bh[nt][0] = f2tf(f0); bh[nt][1] = f2tf(f1);
                if (SPLIT) {
                    bl[nt][0] = f2tf(f0 - __uint_as_float(bh[nt][0]));
                    bl[nt][1] = f2tf(f1 - __uint_as_float(bh[nt][1]));
                }
            }
#pragma unroll
            for (int mt = 0; mt < MT; mt++)
#pragma unroll
                for (int nt = 0; nt < NT; nt++) {
                    mma8(acc[mt][nt], ah[mt], bh[nt]);
                    if (SPLIT) {
                        mma8(acc[mt][nt], al[mt], bh[nt]);
                        mma8(acc[mt][nt], ah[mt], bl[nt]);
                    }
                }
        }
        __syncthreads();
    }

#pragma unroll
    for (int mt = 0; mt < MT; mt++)
#pragma unroll
        for (int nt = 0; nt < NT; nt++) {
            int r0 = bm + wm * MT * 16 + mt * 16 + g;
            int col = bn + wn * NT * 8 + nt * 8 + 2 * tig;
#pragma unroll
            for (int h2 = 0; h2 < 2; h2++) {
                int row = r0 + h2 * 8;
                int lrow = row & (Lc - 1);
                float v0 = acc[mt][nt][h2 * 2 + 0];
                float v1 = acc[mt][nt][h2 * 2 + 1];
                if (bias) { v0 += bias[col]; v1 += bias[col + 1]; }
                if (ACT == 4) {
                    float gt = addRow[row];
                    v0 *= gt; v1 *= gt;
                } else if (addRow) {
                    v0 += addRow[(size_t)lrow * N + col];
                    v1 += addRow[(size_t)lrow * N + col + 1];
                }
                if (ACT == 2) {
                    v0 = 0.5f * v0 * (1.0f + erff(v0 * 0.70710678118654752f));
                    v1 = 0.5f * v1 * (1.0f + erff(v1 * 0.70710678118654752f));
                }
                if (ACT == 3) {
                    v0 = tanhf(v0) * PIF; v1 = tanhf(v1) * PIF;
                    C[(size_t)row * 64 + col]          = cosf(v0);
                    C[(size_t)row * 64 + 32 + col]     = sinf(v0);
                    C[(size_t)row * 64 + col + 1]      = cosf(v1);
                    C[(size_t)row * 64 + 32 + col + 1] = sinf(v1);
                } else {
                    if (resid) {
                        v0 += resid[(size_t)row * N + col];
                        v1 += resid[(size_t)row * N + col + 1];
                    }
                    *reinterpret_cast<float2*>(&C[(size_t)row * N + col]) =
                        make_float2(v0, v1);
                }
            }
        }
}

static constexpr int smemg(int BM, int BN) { return 2 * (BM * 36 + 32 * (BN + 8)) * 4; }

// ---------------- merged skinny GEMM: x @ [w_mem1v | w_off[:256] | w_key] ---
static constexpr int M3_SMEM = 2 * (64 * 36 + 32 * 104) * 4;

__global__ __launch_bounds__(256) void merged3_k(
    const float* __restrict__ A,
    const float* __restrict__ w_mem1v, const float* __restrict__ w_off,
    const float* __restrict__ w_key,
    const float* __restrict__ b_mem1v, const float* __restrict__ b_key,
    const float* __restrict__ pcon, const float* __restrict__ pc,
    const float* __restrict__ ps,
    float* __restrict__ ac, float* __restrict__ offp, float* __restrict__ kq)
{
    const int BM = 64, BK = 32, AP = BK + 4, WP = 104, NT = 6;
    extern __shared__ float sm[];
    float* Ab = sm;
    float* Wb = sm + 2 * BM * AP;
    int tid = threadIdx.x;
    int warp = tid >> 5, lane = tid & 31;
    int wm = warp >> 1, wn = warp & 1;
    int g = lane >> 2, tig = lane & 3;
    int bm = blockIdx.y * BM;
    const float* segp[3] = { w_mem1v, w_off, w_key };

    float acc[NT][4] = {};

    auto issue = [&](int k0, int s) {
#pragma unroll
        for (int i = 0; i < 2; i++) {
            int id = tid + 256 * i;
            int r = id >> 3, c4 = (id & 7) << 2;
            cpa16((uint32_t)__cvta_generic_to_shared(Ab + (s * BM + r) * AP + c4),
                  A + (size_t)(bm + r) * Dc + k0 + c4);
        }
#pragma unroll
        for (int i = 0; i < 3; i++) {
            int id = tid + 256 * i;
            int r = id / 24, c4 = (id % 24) << 2;
            const float* src = segp[c4 >> 5] + (size_t)(k0 + r) * 32 + (c4 & 31);
            cpa16((uint32_t)__cvta_generic_to_shared(Wb + (s * BK + r) * WP + c4), src);
        }
        asm volatile("cp.async.commit_group;");
    };

    issue(0, 0);
    for (int it = 0; it < Dc / BK; it++) {
        asm volatile("cp.async.wait_group 0;");
        __syncthreads();
        if (it + 1 < Dc / BK) issue((it + 1) * BK, (it + 1) & 1);
        int sb = it & 1;
        const float* Ac = Ab + sb * BM * AP;
        const float* Wc = Wb + sb * BK * WP;
#pragma unroll
        for (int ks = 0; ks < 4; ks++) {
            int kk = ks * 8;
            uint32_t ah[4], al[4];
            {
                int r0 = wm * 16 + g;
                float f0 = Ac[r0 * AP + kk + tig],     f1 = Ac[(r0 + 8) * AP + kk + tig];
                float f2 = Ac[r0 * AP + kk + tig + 4], f3 = Ac[(r0 + 8) * AP + kk + tig + 4];
                ah[0] = f2tf(f0); al[0] = f2tf(f0 - __uint_as_float(ah[0]));
                ah[1] = f2tf(f1); al[1] = f2tf(f1 - __uint_as_float(ah[1]));
                ah[2] = f2tf(f2); al[2] = f2tf(f2 - __uint_as_float(ah[2]));
                ah[3] = f2tf(f3); al[3] = f2tf(f3 - __uint_as_float(ah[3]));
            }
            uint32_t bh[NT][2], bl[NT][2];
#pragma unroll
            for (int nt = 0; nt < NT; nt++) {
                int cn = wn * 48 + nt * 8 + g;
                float f0 = Wc[(kk + tig) * WP + cn], f1 = Wc[(kk + tig + 4) * WP + cn];
                bh[nt][0] = f2tf(f0); bl[nt][0] = f2tf(f0 - __uint_as_float(bh[nt][0]));
                bh[nt][1] = f2tf(f1); bl[nt][1] = f2tf(f1 - __uint_as_float(bh[nt][1]));
            }
#pragma unroll
            for (int nt = 0; nt < NT; nt++) {
                mma8(acc[nt], ah, bh[nt]);
                mma8(acc[nt], al, bh[nt]);
                mma8(acc[nt], ah, bl[nt]);
            }
        }
        __syncthreads();
    }

#pragma unroll
    for (int nt = 0; nt < NT; nt++) {
        int col = wn * 48 + nt * 8 + 2 * tig;
        int seg = col >> 5;
#pragma unroll
        for (int h2 = 0; h2 < 2; h2++) {
            int row = bm + wm * 16 + g + h2 * 8;
            int lrow = row & (Lc - 1);
            float v0 = acc[nt][h2 * 2], v1 = acc[nt][h2 * 2 + 1];
            if (seg == 0) {
                int j = col;
                v0 += b_mem1v[j]; v1 += b_mem1v[j + 1];
                ac[(size_t)row * 64 + j]          = pc[lrow * 32 + j] * v0;
                ac[(size_t)row * 64 + 32 + j]     = ps[lrow * 32 + j] * v0;
                ac[(size_t)row * 64 + j + 1]      = pc[lrow * 32 + j + 1] * v1;
                ac[(size_t)row * 64 + 32 + j + 1] = ps[lrow * 32 + j + 1] * v1;
            } else if (seg == 1) {
                int j = col - 32;
                v0 += pcon[lrow * 32 + j]; v1 += pcon[lrow * 32 + j + 1];
                offp[(size_t)row * 32 + j]     = tanhf(v0) * PIF;
                offp[(size_t)row * 32 + j + 1] = tanhf(v1) * PIF;
            } else {
                int j = col - 64;
                v0 += b_key[j]; v1 += b_key[j + 1];
                v0 = tanhf(v0) * PIF; v1 = tanhf(v1) * PIF;
                kq[(size_t)row * 64 + j]          = cosf(v0);
                kq[(size_t)row * 64 + 32 + j]     = sinf(v0);
                kq[(size_t)row * 64 + j + 1]      = cosf(v1);
                kq[(size_t)row * 64 + 32 + j + 1] = sinf(v1);
            }
        }
    }
}

// ---------------- pos precompute -------------------------------------------
__global__ void pos_pre_k(const float* __restrict__ ph, const float* __restrict__ w_off,
                          const float* __restrict__ b_off,
                          float* __restrict__ pc, float* __restrict__ ps,
                          float* __restrict__ pcon)
{
    int idx = blockIdx.x * blockDim.x + threadIdx.x;
    if (idx >= Lc * Pc) return;
    int l = idx >> 5, p = idx & 31;
    float s = b_off[p];
#pragma unroll
    for (int q = 0; q < Pc; q++) s += ph[l * Pc + q] * w_off[(Dc + q) * Pc + p];
    pcon[idx] = s;
    float v = ph[idx];
    pc[idx] = cosf(v);
    ps[idx] = sinf(v);
}

// ---------------- fused gate: dot + sigmoid + in-block cumsum ---------------
__global__ __launch_bounds__(1024) void gate_all_k(
    const float* __restrict__ x, const float* __restrict__ w,
    const float* __restrict__ bsc, float* __restrict__ gate,
    float* __restrict__ gcum)
{
    __shared__ float gs[2048];
    __shared__ float wsum[32];
    int b = blockIdx.x;
    int tid = threadIdx.x, warp = tid >> 5, lane = tid & 31;
    const float* xb = x + (size_t)b * Lc * Dc;
    float bias = bsc[0];
    float wreg[8];
#pragma unroll
    for (int i = 0; i < 8; i++) wreg[i] = w[lane + i * 32];
    for (int r0 = warp * 64; r0 < warp * 64 + 64; r0 += 8) {
        float acc[8] = {};
#pragma unroll
        for (int j = 0; j < 8; j++) {
            const float* xr = xb + (size_t)(r0 + j) * Dc + lane;
#pragma unroll
            for (int i = 0; i < 8; i++) acc[j] += xr[i * 32] * wreg[i];
        }
#pragma unroll
        for (int j = 0; j < 8; j++) {
            float s = acc[j];
#pragma unroll
            for (int o = 16; o; o >>= 1) s += __shfl_xor_sync(0xffffffffu, s, o);
            if (lane == 0) gs[r0 + j] = 1.0f / (1.0f + expf(-(s + bias)));
        }
    }
    __syncthreads();
    float a0 = gs[tid * 2], a1 = gs[tid * 2 + 1];
    float tsum = a0 + a1;
    float sc = tsum;
#pragma unroll
    for (int o = 1; o < 32; o <<= 1) {
        float v = __shfl_up_sync(0xffffffffu, sc, o);
        if (lane >= o) sc += v;
    }
    if (lane == 31) wsum[warp] = sc;
    __syncthreads();
    if (warp == 0) {
        float w0 = wsum[lane];
#pragma unroll
        for (int o = 1; o < 32; o <<= 1) {
            float v = __shfl_up_sync(0xffffffffu, w0, o);
            if (lane >= o) w0 += v;
        }
        wsum[lane] = w0;
    }
    __syncthreads();
    float off = (warp ? wsum[warp - 1] : 0.0f) + (sc - tsum);
    gate[b * Lc + tid * 2]     = a0;
    gate[b * Lc + tid * 2 + 1] = a1;
    gcum[b * Lc + tid * 2]     = off + a0;
    gcum[b * Lc + tid * 2 + 1] = off + a0 + a1;
}

// ---------------- x scan (3 passes, pipelined prefix) -----------------------
__global__ void xscan_sums_k(const float* __restrict__ in, float* __restrict__ csum)
{
    int bc = blockIdx.x, b = bc / NC2, c = bc % NC2, f = threadIdx.x;
    const float* p = in + ((size_t)b * Lc + c * CH2) * 256 + f;
    float s = 0.f;
#pragma unroll
    for (int i = 0; i < CH2; i++) s += p[(size_t)i * 256];
    csum[(size_t)bc * 256 + f] = s;
}

__global__ void xscan_prefix_k(float* __restrict__ csum)
{
    int b = blockIdx.x, f = threadIdx.x;
    size_t base = (size_t)b * NC2 * 256 + f;
    float carry = 0.f;
    float v = csum[base];
    for (int c = 0; c < NC2; c++) {
        size_t idx = base + (size_t)c * 256;
        float vn = (c + 1 < NC2) ? csum[idx + 256] : 0.f;
        csum[idx] = carry;
        carry += v;
        v = vn;
    }
}

__global__ void xscan_apply_k(const float* __restrict__ in, const float* __restrict__ csum,
                              float* __restrict__ ctx)
{
    int bc = blockIdx.x, b = bc / NC2, c = bc % NC2, f = threadIdx.x;
    float carry = csum[(size_t)bc * 256 + f];
    const float* p = in + ((size_t)b * Lc + c * CH2) * 256 + f;
    float* q = ctx + ((size_t)b * Lc + c * CH2) * 256 + f;
#pragma unroll 8
    for (int i = 0; i < CH2; i++) {
        carry += p[(size_t)i * 256];
        q[(size_t)i * 256] = carry * (1.0f / (float)(c * CH2 + i + 1));
    }
}

// ---------------- ac scan: 256-thread sums / prefix / 256-thread apply ------
__global__ __launch_bounds__(256) void ac_sums_k(const float* __restrict__ in,
                                                 float* __restrict__ csum)
{
    __shared__ float gs[4][64];
    int bc = blockIdx.x, tid = threadIdx.x;
    int f = tid & 63, q = tid >> 6;
    const float* p = in + ((size_t)bc * 64 + q * 16) * 64 + f;
    float s = 0.f;
#pragma unroll
    for (int i = 0; i < 16; i++) s += p[(size_t)i * 64];
    gs[q][f] = s;
    __syncthreads();
    if (q == 0) csum[(size_t)bc * 64 + f] = gs[0][f] + gs[1][f] + gs[2][f] + gs[3][f];
}

__global__ void ac_prefix_k(float* __restrict__ csum)
{
    int b = blockIdx.x, f = threadIdx.x;
    size_t base = (size_t)b * NCc * 64 + f;
    float carry = 0.f;
    float v = csum[base];
    for (int c = 0; c < NCc; c++) {
        size_t idx = base + (size_t)c * 64;
        float vn = (c + 1 < NCc) ? csum[idx + 64] : 0.f;
        csum[idx] = carry;
        carry += v;
        v = vn;
    }
}

// 256-thread: 4-way row-split chunk scan + wide posret epilogue
__global__ __launch_bounds__(256) void ac_apply_posret_k(
    const float* __restrict__ ac, const float* __restrict__ csum,
    const float* __restrict__ offp, const float* __restrict__ pc,
    const float* __restrict__ ps, float* __restrict__ pr)
{
    __shared__ float sh[64][65];
    __shared__ float gsum[4][64];
    int bc = blockIdx.x, tid = threadIdx.x;
    int f = tid & 63, q = tid >> 6;
    size_t rowbase = (size_t)bc * 64;

    const float* p = ac + (rowbase + q * 16) * 64 + f;
    float vals[16];
    float s = 0.f;
#pragma unroll
    for (int i = 0; i < 16; i++) { s += p[(size_t)i * 64]; vals[i] = s; }
    gsum[q][f] = s;
    __syncthreads();
    float base = csum[(size_t)bc * 64 + f];
#pragma unroll
    for (int j = 0; j < 3; j++)
        if (j < q) base += gsum[j][f];
    __syncthreads();
#pragma unroll
    for (int i = 0; i < 16; i++) sh[q * 16 + i][f] = base + vals[i];
    __syncthreads();

#pragma unroll
    for (int j = 0; j < 8; j++) {
        int idx = j * 256 + tid;
        int i = idx >> 5, pp = idx & 31;
        size_t m = rowbase + i;
        int l = (int)(m & (Lc - 1));
        float o = offp[m * 32 + pp];
        float oc = cosf(o), os = sinf(o);
        float pcv = pc[l * 32 + pp], psv = ps[l * 32 + pp];
        float qc = pcv * oc - psv * os;
        float qs = psv * oc + pcv * os;
        pr[m * 32 + pp] = (sh[i][pp] * qc + sh[i][32 + pp] * qs) * INV_SQRT_P;
    }
}

// ---------------- chunk state delta via tf32 mma ---------------------------
__global__ __launch_bounds__(256) void chunk_delta_k(const float* __restrict__ U,
                                                     const float* __restrict__ GV,
                                                     float* __restrict__ dS)
{
    __shared__ float Us[64][72];
    __shared__ float Gs[64][72];
    int bc = blockIdx.x;
    size_t rowbase = (size_t)bc * 64;
    int tid = threadIdx.x;
    int warp = tid >> 5, lane = tid & 31;
    int wm = warp >> 2, wn = warp & 3;
    int g = lane >> 2, tig = lane & 3;

#pragma unroll
    for (int i = 0; i < 4; i++) {
        int id = tid + 256 * i;
        int t = id >> 4, f = (id & 15) << 2;
        float4 v = *reinterpret_cast<const float4*>(U + (rowbase + t) * 64 + f);
        v.x = f2tf_f(v.x); v.y = f2tf_f(v.y); v.z = f2tf_f(v.z); v.w = f2tf_f(v.w);
        *reinterpret_cast<float4*>(&Us[t][f]) = v;
    }

    for (int dt = 0; dt < 4; dt++) {
        __syncthreads();
#pragma unroll
        for (int i = 0; i < 4; i++) {
            int id = tid + 256 * i;
            int t = id >> 4, d = (id & 15) << 2;
            float4 v = *reinterpret_cast<const float4*>(GV + (rowbase + t) * 256 + dt * 64 + d);
            v.x = f2tf_f(v.x); v.y = f2tf_f(v.y); v.z = f2tf_f(v.z); v.w = f2tf_f(v.w);
            *reinterpret_cast<float4*>(&Gs[t][d]) = v;
        }
        __syncthreads();

        float acc[2][2][4] = {};
#pragma unroll
        for (int ks = 0; ks < 8; ks++) {
            int kk = ks * 8;
            uint32_t a[2][4], b[2][2];
#pragma unroll
            for (int mt = 0; mt < 2; mt++) {
                int f0 = wm * 32 + mt * 16 + g;
                a[mt][0] = __float_as_uint(Us[kk + tig][f0]);
                a[mt][1] = __float_as_uint(Us[kk + tig][f0 + 8]);
                a[mt][2] = __float_as_uint(Us[kk + tig + 4][f0]);
                a[mt][3] = __float_as_uint(Us[kk + tig + 4][f0 + 8]);
            }
#pragma unroll
            for (int nt = 0; nt < 2; nt++) {
                int d0 = wn * 16 + nt * 8 + g;
                b[nt][0] = __float_as_uint(Gs[kk + tig][d0]);
                b[nt][1] = __float_as_uint(Gs[kk + tig + 4][d0]);
            }
#pragma unroll
            for (int mt = 0; mt < 2; mt++)
#pragma unroll
                for (int nt = 0; nt < 2; nt++) mma8(acc[mt][nt], a[mt], b[nt]);
        }
#pragma unroll
        for (int mt = 0; mt < 2; mt++)
#pragma unroll
            for (int nt = 0; nt < 2; nt++) {
                int f0 = wm * 32 + mt * 16 + g;
                int d = dt * 64 + wn * 16 + nt * 8 + 2 * tig;
#pragma unroll
                for (int h2 = 0; h2 < 2; h2++) {
                    *reinterpret_cast<float2*>(&dS[((size_t)bc * 64 + f0 + h2 * 8) * 256 + d]) =
                        make_float2(acc[mt][nt][h2 * 2], acc[mt][nt][h2 * 2 + 1]);
                }
            }
    }
}

// ---------------- exclusive prefix of chunk states (pipelined) --------------
__global__ void state_prefix_k(float* __restrict__ dS)
{
    int idx = blockIdx.x * blockDim.x + threadIdx.x;
    int b = idx >> 14;
    int fd = idx & 16383;
    size_t base = (size_t)b * NCc * 16384 + fd;
    float carry = 0.f;
    float v = dS[base];
    for (int c = 0; c < NCc; c++) {
        size_t o = base + (size_t)c * 16384;
        float vn = (c + 1 < NCc) ? dS[o + 16384] : 0.f;
        dS[o] = carry;
        carry += v;
        v = vn;
    }
}

// ---------------- kv pass3 via tf32 mma + fused layernorm -------------------
static constexpr int P3_PITCH = 68;
static constexpr size_t SMEM_P3 = 5 * 64 * P3_PITCH * sizeof(float);

__global__ __launch_bounds__(256) void kv_pass3_mma_k(
    const float* __restrict__ Kq, const float* __restrict__ U,
    const float* __restrict__ GV, const float* __restrict__ Spre,
    const float* __restrict__ gcum, const float* __restrict__ comb,
    const float* __restrict__ lng, const float* __restrict__ lnbv,
    float* __restrict__ outb)
{
    extern __shared__ float dyn[];
    float (*Kqs)[P3_PITCH] = reinterpret_cast<float(*)[P3_PITCH]>(dyn);
    float (*Us)[P3_PITCH]  = reinterpret_cast<float(*)[P3_PITCH]>(dyn + 64 * P3_PITCH);
    float (*Ss)[P3_PITCH]  = reinterpret_cast<float(*)[P3_PITCH]>(dyn + 2 * 64 * P3_PITCH);
    float (*P1)[P3_PITCH]  = reinterpret_cast<float(*)[P3_PITCH]>(dyn + 3 * 64 * P3_PITCH);
    float (*P2)[P3_PITCH]  = reinterpret_cast<float(*)[P3_PITCH]>(dyn + 4 * 64 * P3_PITCH);
    __shared__ float ws[4][64], ws2[4][64];

    int bc = blockIdx.x;
    size_t rowbase = (size_t)bc * 64;
    int tid = threadIdx.x;
    int warp = tid >> 5, lane = tid & 31;
    int wm = warp >> 2, wn = warp & 3;
    int g = lane >> 2, tig = lane & 3;

#pragma unroll
    for (int i = 0; i < 4; i++) {
        int id = tid + 256 * i;
        int t = id >> 4, f = (id & 15) << 2;
        float4 v = *reinterpret_cast<const float4*>(Kq + (rowbase + t) * 64 + f);
        v.x = f2tf_f(v.x); v.y = f2tf_f(v.y); v.z = f2tf_f(v.z); v.w = f2tf_f(v.w);
        *reinterpret_cast<float4*>(&Kqs[t][f]) = v;
        float4 w = *reinterpret_cast<const float4*>(U + (rowbase + t) * 64 + f);
        w.x = f2tf_f(w.x); w.y = f2tf_f(w.y); w.z = f2tf_f(w.z); w.w = f2tf_f(w.w);
        *reinterpret_cast<float4*>(&Us[t][f]) = w;
    }
    __syncthreads();

    {
        float sacc[2][2][4] = {};
#pragma unroll
        for (int ks = 0; ks < 8; ks++) {
            int kk = ks * 8;
            uint32_t a[2][4], b[2][2];
#pragma unroll
            for (int mt = 0; mt < 2; mt++) {
                int r0 = wm * 32 + mt * 16 + g;
                a[mt][0] = __float_as_uint(Kqs[r0][kk + tig]);
                a[mt][1] = __float_as_uint(Kqs[r0 + 8][kk + tig]);
                a[mt][2] = __float_as_uint(Kqs[r0][kk + tig + 4]);
                a[mt][3] = __float_as_uint(Kqs[r0 + 8][kk + tig + 4]);
            }
#pragma unroll
            for (int nt = 0; nt < 2; nt++) {
                int cn = wn * 16 + nt * 8 + g;
                b[nt][0] = __float_as_uint(Us[cn][kk + tig]);
                b[nt][1] = __float_as_uint(Us[cn][kk + tig + 4]);
            }
#pragma unroll
            for (int mt = 0; mt < 2; mt++)
#pragma unroll
                for (int nt = 0; nt < 2; nt++) mma8(sacc[mt][nt], a[mt], b[nt]);
        }
#pragma unroll
        for (int mt = 0; mt < 2; mt++)
#pragma unroll
            for (int nt = 0; nt < 2; nt++)
#pragma unroll
                for (int h2 = 0; h2 < 2; h2++) {
                    int row = wm * 32 + mt * 16 + h2 * 8 + g;
                    int col = wn * 16 + nt * 8 + 2 * tig;
                    float v0 = (col     <= row) ? sacc[mt][nt][h2 * 2]     : 0.f;
                    float v1 = (col + 1 <= row) ? sacc[mt][nt][h2 * 2 + 1] : 0.f;
                    Ss[row][col]     = f2tf_f(v0);
                    Ss[row][col + 1] = f2tf_f(v1);
                }
    }
    __syncthreads();

    float val[4][2][2][4];
#pragma unroll
    for (int p = 0; p < 4; p++)
#pragma unroll
        for (int mt = 0; mt < 2; mt++)
#pragma unroll
            for (int nt = 0; nt < 2; nt++)
#pragma unroll
                for (int j = 0; j < 4; j++) val[p][mt][nt][j] = 0.f;

    for (int p = 0; p < 4; p++) {
#pragma unroll
        for (int i = 0; i < 4; i++) {
            int id = tid + 256 * i;
            int t = id >> 4, d = (id & 15) << 2;
            float4 v = *reinterpret_cast<const float4*>(GV + (rowbase + t) * 256 + p * 64 + d);
            v.x = f2tf_f(v.x); v.y = f2tf_f(v.y); v.z = f2tf_f(v.z); v.w = f2tf_f(v.w);
            *reinterpret_cast<float4*>(&P1[t][d]) = v;
            float4 w = *reinterpret_cast<const float4*>(Spre + ((size_t)bc * 64 + t) * 256 + p * 64 + d);
            w.x = f2tf_f(w.x); w.y = f2tf_f(w.y); w.z = f2tf_f(w.z); w.w = f2tf_f(w.w);
            *reinterpret_cast<float4*>(&P2[t][d]) = w;
        }
        __syncthreads();
#pragma unroll
        for (int ks = 0; ks < 8; ks++) {
            int kk = ks * 8;
            uint32_t a1[2][4], a2[2][4], b1[2][2], b2[2][2];
#pragma unroll
            for (int mt = 0; mt < 2; mt++) {
                int r0 = wm * 32 + mt * 16 + g;
                a1[mt][0] = __float_as_uint(Ss[r0][kk + tig]);
                a1[mt][1] = __float_as_uint(Ss[r0 + 8][kk + tig]);
                a1[mt][2] = __float_as_uint(Ss[r0][kk + tig + 4]);
                a1[mt][3] = __float_as_uint(Ss[r0 + 8][kk + tig + 4]);
                a2[mt][0] = __float_as_uint(Kqs[r0][kk + tig]);
                a2[mt][1] = __float_as_uint(Kqs[r0 + 8][kk + tig]);
                a2[mt][2] = __float_as_uint(Kqs[r0][kk + tig + 4]);
                a2[mt][3] = __float_as_uint(Kqs[r0 + 8][kk + tig + 4]);
            }
#pragma unroll
            for (int nt = 0; nt < 2; nt++) {
                int cn = wn * 16 + nt * 8 + g;
                b1[nt][0] = __float_as_uint(P1[kk + tig][cn]);
                b1[nt][1] = __float_as_uint(P1[kk + tig + 4][cn]);
                b2[nt][0] = __float_as_uint(P2[kk + tig][cn]);
                b2[nt][1] = __float_as_uint(P2[kk + tig + 4][cn]);
            }
#pragma unroll
            for (int mt = 0; mt < 2; mt++)
#pragma unroll
                for (int nt = 0; nt < 2; nt++) {
                    mma8(val[p][mt][nt], a1[mt], b1[nt]);
                    mma8(val[p][mt][nt], a2[mt], b2[nt]);
                }
        }
        __syncthreads();
    }

    float scl4[4];
#pragma unroll
    for (int mt = 0; mt < 2; mt++)
#pragma unroll
        for (int h2 = 0; h2 < 2; h2++) {
            int row = wm * 32 + mt * 16 + h2 * 8 + g;
            float gc = gcum[rowbase + row];
            scl4[mt * 2 + h2] = rsqrtf(fmaxf(gc, 1.0f)) * INV_SQRT_P;
        }
    float s[4] = {}, s2[4] = {};
#pragma unroll
    for (int p = 0; p < 4; p++)
#pragma unroll
        for (int mt = 0; mt < 2; mt++)
#pragma unroll
            for (int nt = 0; nt < 2; nt++)
#pragma unroll
                for (int h2 = 0; h2 < 2; h2++) {
                    int row = wm * 32 + mt * 16 + h2 * 8 + g;
                    int col = p * 64 + wn * 16 + nt * 8 + 2 * tig;
                    int slot = mt * 2 + h2;
                    float2 cb = *reinterpret_cast<const float2*>(
                        &comb[(rowbase + row) * 256 + col]);
                    float v0 = cb.x + val[p][mt][nt][h2 * 2]     * scl4[slot];
                    float v1 = cb.y + val[p][mt][nt][h2 * 2 + 1] * scl4[slot];
                    val[p][mt][nt][h2 * 2] = v0;
                    val[p][mt][nt][h2 * 2 + 1] = v1;
                    s[slot] += v0 + v1;
                    s2[slot] += v0 * v0 + v1 * v1;
                }
#pragma unroll
    for (int o = 1; o <= 2; o <<= 1)
#pragma unroll
        for (int i = 0; i < 4; i++) {
            s[i]  += __shfl_xor_sync(0xffffffffu, s[i],  o);
            s2[i] += __shfl_xor_sync(0xffffffffu, s2[i], o);
        }
    if (tig == 0) {
#pragma unroll
        for (int mt = 0; mt < 2; mt++)
#pragma unroll
            for (int h2 = 0; h2 < 2; h2++) {
                int row = wm * 32 + mt * 16 + h2 * 8 + g;
                ws[wn][row]  = s[mt * 2 + h2];
                ws2[wn][row] = s2[mt * 2 + h2];
            }
    }
    __syncthreads();
    float mean4[4], rstd4[4];
#pragma unroll
    for (int mt = 0; mt < 2; mt++)
#pragma unroll
        for (int h2 = 0; h2 < 2; h2++) {
            int row = wm * 32 + mt * 16 + h2 * 8 + g;
            float St = ws[0][row] + ws[1][row] + ws[2][row] + ws[3][row];
            float S2t = ws2[0][row] + ws2[1][row] + ws2[2][row] + ws2[3][row];
            float mean = St * (1.0f / 256.0f);
            float var = S2t * (1.0f / 256.0f) - mean * mean;
            mean4[mt * 2 + h2] = mean;
            rstd4[mt * 2 + h2] = rsqrtf(var + 1e-5f);
        }
#pragma unroll
    for (int p = 0; p < 4; p++)
#pragma unroll
        for (int nt = 0; nt < 2; nt++) {
            int col = p * 64 + wn * 16 + nt * 8 + 2 * tig;
            float g0 = lng[col], g1 = lng[col + 1];
            float b0 = lnbv[col], b1 = lnbv[col + 1];
#pragma unroll
            for (int mt = 0; mt < 2; mt++)
#pragma unroll
                for (int h2 = 0; h2 < 2; h2++) {
                    int row = wm * 32 + mt * 16 + h2 * 8 + g;
                    int slot = mt * 2 + h2;
                    float v0 = (val[p][mt][nt][h2 * 2]     - mean4[slot]) * rstd4[slot] * g0 + b0;
                    float v1 = (val[p][mt][nt][h2 * 2 + 1] - mean4[slot]) * rstd4[slot] * g1 + b1;
                    *reinterpret_cast<float2*>(&outb[(rowbase + row) * 256 + col]) =
                        make_float2(v0, v1);
                }
        }
}

// ---------------- stream/event context (created once, outside capture) -----
namespace {
struct Ctx {
    cudaStream_t s1, s2;
    cudaEvent_t eR1, eR2, eGV, eA;
    Ctx() {
        cudaStreamCreateWithFlags(&s1, cudaStreamNonBlocking);
        cudaStreamCreateWithFlags(&s2, cudaStreamNonBlocking);
        cudaEventCreateWithFlags(&eR1, cudaEventDisableTiming);
        cudaEventCreateWithFlags(&eR2, cudaEventDisableTiming);
        cudaEventCreateWithFlags(&eGV, cudaEventDisableTiming);
        cudaEventCreateWithFlags(&eA, cudaEventDisableTiming);
        cudaFuncSetAttribute(kv_pass3_mma_k,
                             cudaFuncAttributeMaxDynamicSharedMemorySize, (int)SMEM_P3);
        cudaFuncSetAttribute(merged3_k,
                             cudaFuncAttributeMaxDynamicSharedMemorySize, M3_SMEM);
        cudaFuncSetAttribute(tgemm_k<128, 64, 2, 4, 0, 0, 0>,
                             cudaFuncAttributeMaxDynamicSharedMemorySize, smemg(128, 64));
        cudaFuncSetAttribute(tgemm_k<128, 64, 2, 4, 4, 0, 0>,
                             cudaFuncAttributeMaxDynamicSharedMemorySize, smemg(128, 64));
        cudaFuncSetAttribute(tgemm_k<128, 64, 2, 4, 2, 0, 1>,
                             cudaFuncAttributeMaxDynamicSharedMemorySize, smemg(128, 64));
        cudaFuncSetAttribute(tgemm_k<64, 32, 1, 2, 3, 1, 0>,
                             cudaFuncAttributeMaxDynamicSharedMemorySize, smemg(64, 32));
    }
};
Ctx& C() { static Ctx c; return c; }
}

// ---------------- host launch -----------------------------------------------
extern "C" void kernel_launch(void* const* d_in, const int* in_sizes, int n_in,
                              void* d_out, int out_size)
{
    (void)in_sizes; (void)n_in; (void)out_size;
    const float* x        = (const float*)d_in[0];
    const float* pos_ph   = (const float*)d_in[1];
    const float* w_mem1v  = (const float*)d_in[2];
    const float* b_mem1v  = (const float*)d_in[3];
    const float* w_mem1o  = (const float*)d_in[4];
    const float* b_mem1o  = (const float*)d_in[5];
    const float* w_off    = (const float*)d_in[6];
    const float* b_off    = (const float*)d_in[7];
    const float* w_key    = (const float*)d_in[8];
    const float* b_key    = (const float*)d_in[9];
    const float* w_val    = (const float*)d_in[10];
    const float* b_val    = (const float*)d_in[11];
    const float* w_sk1    = (const float*)d_in[12];
    const float* b_sk1    = (const float*)d_in[13];
    const float* w_sk2    = (const float*)d_in[14];
    const float* b_sk2    = (const float*)d_in[15];
    const float* w_gate   = (const float*)d_in[16];
    const float* b_gate   = (const float*)d_in[17];
    const float* ln_g     = (const float*)d_in[18];
    const float* ln_b     = (const float*)d_in[19];
    const float* w_out    = (const float*)d_in[20];
    const float* b_out    = (const float*)d_in[21];
    float* out = (float*)d_out;

    float* buf = nullptr;
    cudaGetSymbolAddress((void**)&buf, g_buf);
    float* csum  = buf + OFF_CSUM;
    float* offp  = buf + OFF_OFFP;
    float* pcon  = buf + OFF_PCON;
    float* pc    = buf + OFF_PC;
    float* ps    = buf + OFF_PS;
    float* ac    = buf + OFF_AC;
    float* pr    = buf + OFF_POSRET;
    float* kq    = buf + OFF_KQ;
    float* u     = buf + OFF_U;
    float* gate  = buf + OFF_GATE;
    float* gcum  = buf + OFF_GCUM;
    float* gv    = buf + OFF_GV;
    float* ctx   = buf + OFF_CTX;
    float* h     = buf + OFF_H;
    float* csum2 = buf + OFF_CSUM2;
    float* dS    = buf + OFF_DS;
    float* comb  = buf + OFF_COMB;
    float* lnb   = buf + OFF_LN;

    Ctx& c = C();
    dim3 gS(1, Mc / 64);
    dim3 gW(4, Mc / 128);
    const int SS = smemg(64, 32), SW = smemg(128, 64);

    // fork
    cudaEventRecord(c.eR1, 0);
    cudaStreamWaitEvent(c.s1, c.eR1, 0);
    cudaEventRecord(c.eR2, 0);
    cudaStreamWaitEvent(c.s2, c.eR2, 0);

    // ---- path A (s1): merged x-projections + mem1 ----
    pos_pre_k<<<(Lc * Pc) / 256, 256, 0, c.s1>>>(pos_ph, w_off, b_off, pc, ps, pcon);
    merged3_k<<<gS, 256, M3_SMEM, c.s1>>>(x, w_mem1v, w_off, w_key, b_mem1v, b_key,
                                          pcon, pc, ps, ac, offp, kq);
    ac_sums_k<<<Bc * NCc, 256, 0, c.s1>>>(ac, csum2);
    ac_prefix_k<<<Bc, 64, 0, c.s1>>>(csum2);
    ac_apply_posret_k<<<Bc * NCc, 256, 0, c.s1>>>(ac, csum2, offp, pc, ps, pr);
    tgemm_k<128, 64, 2, 4, 0, 0, 0><<<gW, 256, SW, c.s1>>>(pr, nullptr, w_mem1o, b_mem1o, nullptr, nullptr, comb, Dc, Pc);
    cudaEventRecord(c.eA, c.s1);

    // ---- path B (s2): gate + gated values ----
    gate_all_k<<<Bc, 1024, 0, c.s2>>>(x, w_gate, b_gate, gate, gcum);
    tgemm_k<128, 64, 2, 4, 4, 0, 0><<<gW, 256, SW, c.s2>>>(x, nullptr, w_val, b_val, gate, nullptr, gv, Dc, Dc);
    cudaEventRecord(c.eGV, c.s2);

    // ---- path D (default): storage phases + attention ----
    xscan_sums_k<<<Bc * NC2, 256>>>(x, csum);
    xscan_prefix_k<<<Bc, 256>>>(csum);
    xscan_apply_k<<<Bc * NC2, 256>>>(x, csum, ctx);
    tgemm_k<128, 64, 2, 4, 2, 0, 1><<<gW, 256, SW>>>(x, ctx, w_sk1, b_sk1, nullptr, nullptr, h, Dc, 2 * Dc);
    tgemm_k<64, 32, 1, 2, 3, 1, 0><<<gS, 256, SS>>>(h, nullptr, w_sk2, b_sk2, nullptr, nullptr, u, Pc, Dc);
    cudaStreamWaitEvent(0, c.eGV, 0);
    chunk_delta_k<<<Bc * NCc, 256>>>(u, gv, dS);
    state_prefix_k<<<(Bc * 64 * 256) / 256, 256>>>(dS);
    cudaStreamWaitEvent(0, c.eA, 0);
    kv_pass3_mma_k<<<Bc * NCc, 256, SMEM_P3>>>(kq, u, gv, dS, gcum, comb, ln_g, ln_b, lnb);
    tgemm_k<128, 64, 2, 4, 0, 0, 0><<<gW, 256, SW>>>(lnb, nullptr, w_out, b_out, nullptr, x, out, Dc, Dc);
}